// round 4
// baseline (speedup 1.0000x reference)
#include <cuda_runtime.h>

#define THREADS 256
#define OPT 8
#define TILE (THREADS * OPT)       // 2048 outputs per block
#define PTAPS 32                   // pair-taps (covers 64 padded taps)
#define KPAD 64
#define SMEM_F (TILE + KPAD)       // 2112 floats; max index 2*(1023+31)+1 = 2109 < 2112

typedef unsigned long long ull;

__device__ __forceinline__ ull pk2(float lo, float hi) {
    ull r; asm("mov.b64 %0, {%1, %2};" : "=l"(r) : "f"(lo), "f"(hi)); return r;
}
__device__ __forceinline__ void upk2(ull v, float& lo, float& hi) {
    asm("mov.b64 {%0, %1}, %2;" : "=f"(lo), "=f"(hi) : "l"(v));
}
__device__ __forceinline__ ull ffma2(ull a, ull b, ull c) {
    ull d; asm("fma.rn.f32x2 %0, %1, %2, %3;" : "=l"(d) : "l"(a), "l"(b), "l"(c)); return d;
}

__global__ __launch_bounds__(THREADS) void fir3_kernel(
    const float* __restrict__ u, const float* __restrict__ kern,
    float* __restrict__ out, int cols, int out_cols, int K)
{
    __shared__ float      s_u[SMEM_F];
    __shared__ ulonglong2 s_w[PTAPS];   // (WE[t], WO[t]) interleaved: one LDS.128 broadcast/tap

    const int tid  = threadIdx.x;
    const int row  = blockIdx.y;
    const int base = blockIdx.x * TILE;
    const float* urow = u + (size_t)row * cols;

    // Weight tables. w[k] = kern[K-1-k] (reversed), zero-padded.
    // WE[t] = (w[2t], w[2t+1])   -> even outputs
    // WO[t] = (w[2t-1], w[2t])   -> odd outputs (one-tap shift), w[-1] = 0
    if (tid < PTAPS) {
        const int t = tid;
        const float w_e0 = (2*t     < K) ? kern[K - 1 - 2*t]       : 0.0f;
        const float w_e1 = (2*t + 1 < K) ? kern[K - 1 - (2*t + 1)] : 0.0f;
        const float w_o0 = (2*t >= 1 && 2*t - 1 < K) ? kern[K - 1 - (2*t - 1)] : 0.0f;
        s_w[t] = make_ulonglong2(pk2(w_e0, w_e1), pk2(w_o0, w_e0));
    }

    // Stage input tile (coalesced float4, zero-fill past end of row).
    for (int q = tid; q < SMEM_F / 4; q += THREADS) {
        const int gi = base + q * 4;
        float4 v;
        if (gi + 3 < cols) {
            v = *reinterpret_cast<const float4*>(urow + gi);
        } else {
            v.x = (gi + 0 < cols) ? urow[gi + 0] : 0.0f;
            v.y = (gi + 1 < cols) ? urow[gi + 1] : 0.0f;
            v.z = (gi + 2 < cols) ? urow[gi + 2] : 0.0f;
            v.w = (gi + 3 < cols) ? urow[gi + 3] : 0.0f;
        }
        reinterpret_cast<float4*>(s_u)[q] = v;
    }
    __syncthreads();

    const ull* pu = reinterpret_cast<const ull*>(s_u);   // aligned pairs p[i]=(u[2i],u[2i+1])

    // 4 streams: stream j computes outputs base + 2*(tid+256j) and +1.
    ull Ae0=0, Ae1=0, Ae2=0, Ae3=0;
    ull Ao0=0, Ao1=0, Ao2=0, Ao3=0;

    #pragma unroll
    for (int t = 0; t < PTAPS; ++t) {
        const ulonglong2 W = s_w[t];                     // LDS.128 broadcast
        const ull P0 = pu[tid + 256*0 + t];              // LDS.64, lane-consecutive, imm offsets
        const ull P1 = pu[tid + 256*1 + t];
        const ull P2 = pu[tid + 256*2 + t];
        const ull P3 = pu[tid + 256*3 + t];
        Ae0 = ffma2(P0, W.x, Ae0);  Ao0 = ffma2(P0, W.y, Ao0);
        Ae1 = ffma2(P1, W.x, Ae1);  Ao1 = ffma2(P1, W.y, Ao1);
        Ae2 = ffma2(P2, W.x, Ae2);  Ao2 = ffma2(P2, W.y, Ao2);
        Ae3 = ffma2(P3, W.x, Ae3);  Ao3 = ffma2(P3, W.y, Ao3);
    }

    float* orow = out + (size_t)row * out_cols;

    #pragma unroll
    for (int j = 0; j < 4; ++j) {
        const ull Ae = (j==0)?Ae0:(j==1)?Ae1:(j==2)?Ae2:Ae3;
        const ull Ao = (j==0)?Ao0:(j==1)?Ao1:(j==2)?Ao2:Ao3;
        float e0,e1,d0,d1;
        upk2(Ae, e0, e1); upk2(Ao, d0, d1);
        const int o = base + 2 * (tid + 256*j);
        const float re = e0 + e1;     // even output
        const float ro = d0 + d1;     // odd output
        if (o + 1 < out_cols) {
            *reinterpret_cast<float2*>(orow + o) = make_float2(re, ro);  // 8B-aligned
        } else if (o < out_cols) {
            orow[o] = re;
        }
    }
}

extern "C" void kernel_launch(void* const* d_in, const int* in_sizes, int n_in,
                              void* d_out, int out_size)
{
    const float* u    = (const float*)d_in[0];
    const float* kern = (const float*)d_in[1];
    float*       out  = (float*)d_out;

    const int S0 = in_sizes[0];
    const int K  = in_sizes[1];
    const int rows     = (S0 - out_size) / (K - 1);
    const int cols     = S0 / rows;
    const int out_cols = cols - K + 1;

    dim3 grid((out_cols + TILE - 1) / TILE, rows);
    fir3_kernel<<<grid, THREADS>>>(u, kern, out, cols, out_cols, K);
}

// round 6
// speedup vs baseline: 1.1894x; 1.1894x over previous
#include <cuda_runtime.h>

#define THREADS 256
#define OPT 16                      // outputs per thread (8 pairs)
#define TILE (THREADS * OPT)        // 4096 outputs per block
#define PTAPS 32                    // pair-taps (covers 64 padded taps)
#define KPAD 64
#define SMEM_F (TILE + KPAD)        // 4160 floats = 2080 pairs
#define NPAIR (SMEM_F / 2)

typedef unsigned long long ull;

__device__ __forceinline__ ull pk2(float lo, float hi) {
    ull r; asm("mov.b64 %0, {%1, %2};" : "=l"(r) : "f"(lo), "f"(hi)); return r;
}
__device__ __forceinline__ void upk2(ull v, float& lo, float& hi) {
    asm("mov.b64 {%0, %1}, %2;" : "=f"(lo), "=f"(hi) : "l"(v));
}
__device__ __forceinline__ ull ffma2(ull a, ull b, ull c) {
    ull d; asm("fma.rn.f32x2 %0, %1, %2, %3;" : "=l"(d) : "l"(a), "l"(b), "l"(c)); return d;
}

__global__ __launch_bounds__(THREADS) void fir5_kernel(
    const float* __restrict__ u, const float* __restrict__ kern,
    float* __restrict__ out, int cols, int out_cols, int K)
{
    __shared__ float      s_u[SMEM_F];
    __shared__ ulonglong2 s_w[PTAPS];   // (WE[t], WO[t]); one LDS.128 broadcast per tap

    const int tid  = threadIdx.x;
    const int row  = blockIdx.y;
    const int base = blockIdx.x * TILE;
    const float* urow = u + (size_t)row * cols;

    // w[k] = kern[K-1-k] reversed, zero-padded to 64.
    // WE[t] = (w[2t], w[2t+1])  : even outputs.  WO[t] = (w[2t-1], w[2t]) : odd outputs.
    if (tid < PTAPS) {
        const int t = tid;
        const float we0 = (2*t     < K) ? kern[K - 1 - 2*t]       : 0.0f;
        const float we1 = (2*t + 1 < K) ? kern[K - 1 - (2*t + 1)] : 0.0f;
        const float wo0 = (2*t >= 1 && 2*t - 1 < K) ? kern[K - 1 - (2*t - 1)] : 0.0f;
        s_w[t] = make_ulonglong2(pk2(we0, we1), pk2(wo0, we0));
    }

    // Stage input tile (coalesced float4, zero-fill past row end).
    for (int q = tid; q < SMEM_F / 4; q += THREADS) {
        const int gi = base + q * 4;
        float4 v;
        if (gi + 3 < cols) {
            v = *reinterpret_cast<const float4*>(urow + gi);
        } else {
            v.x = (gi + 0 < cols) ? urow[gi + 0] : 0.0f;
            v.y = (gi + 1 < cols) ? urow[gi + 1] : 0.0f;
            v.z = (gi + 2 < cols) ? urow[gi + 2] : 0.0f;
            v.w = (gi + 3 < cols) ? urow[gi + 3] : 0.0f;
        }
        reinterpret_cast<float4*>(s_u)[q] = v;
    }
    __syncthreads();

    const ull* pu = reinterpret_cast<const ull*>(s_u);   // aligned pairs P[i]=(u[2i],u[2i+1])
    const int m0 = tid * (OPT / 2);                      // first output-pair index (local)

    // Register window: win[r] = P[m0 + t + r], r = 0..7.
    ull win[8];
    #pragma unroll
    for (int r = 0; r < 8; ++r) win[r] = pu[m0 + r];

    ull Ae[8], Ao[8];
    #pragma unroll
    for (int r = 0; r < 8; ++r) { Ae[r] = 0ull; Ao[r] = 0ull; }

    #pragma unroll
    for (int t = 0; t < PTAPS; ++t) {
        const ulonglong2 W = s_w[t];                     // broadcast
        #pragma unroll
        for (int r = 0; r < 8; ++r) {
            Ae[r] = ffma2(win[r], W.x, Ae[r]);
            Ao[r] = ffma2(win[r], W.y, Ao[r]);
        }
        #pragma unroll
        for (int r = 0; r < 7; ++r) win[r] = win[r + 1]; // renamed by unroll
        win[7] = pu[m0 + t + 8];                         // FIX: next iter needs P[m0+(t+1)+7]
    }

    // Horizontal sums -> 16 consecutive outputs.
    float res[16];
    #pragma unroll
    for (int r = 0; r < 8; ++r) {
        float e0, e1, d0, d1;
        upk2(Ae[r], e0, e1); upk2(Ao[r], d0, d1);
        res[2*r + 0] = e0 + e1;
        res[2*r + 1] = d0 + d1;
    }

    const int oc = base + tid * OPT;                     // 16-aligned
    float* orow = out + (size_t)row * out_cols;
    if (oc + OPT - 1 < out_cols) {
        #pragma unroll
        for (int q = 0; q < OPT / 4; ++q) {
            float4 v; v.x = res[4*q]; v.y = res[4*q+1]; v.z = res[4*q+2]; v.w = res[4*q+3];
            *reinterpret_cast<float4*>(orow + oc + 4*q) = v;
        }
    } else {
        #pragma unroll
        for (int k = 0; k < OPT; ++k)
            if (oc + k < out_cols) orow[oc + k] = res[k];
    }
}

extern "C" void kernel_launch(void* const* d_in, const int* in_sizes, int n_in,
                              void* d_out, int out_size)
{
    const float* u    = (const float*)d_in[0];
    const float* kern = (const float*)d_in[1];
    float*       out  = (float*)d_out;

    const int S0 = in_sizes[0];
    const int K  = in_sizes[1];
    const int rows     = (S0 - out_size) / (K - 1);
    const int cols     = S0 / rows;
    const int out_cols = cols - K + 1;

    dim3 grid((out_cols + TILE - 1) / TILE, rows);
    fir5_kernel<<<grid, THREADS>>>(u, kern, out, cols, out_cols, K);
}

// round 7
// speedup vs baseline: 1.4816x; 1.2457x over previous
#include <cuda_runtime.h>

#define THREADS 256
#define OPT 16                      // outputs per thread (8 pairs)
#define TILE (THREADS * OPT)        // 4096 outputs per block
#define PTAPS 32                    // pair-taps (covers 64 padded taps)
#define KPAD 64
#define NPAIR ((TILE + KPAD) / 2)   // 2080 data pairs
#define NSLOT (NPAIR + NPAIR / 8)   // 2340 skewed slots (pair i -> slot i + i/8)

typedef unsigned long long ull;

__device__ __forceinline__ ull pk2(float lo, float hi) {
    ull r; asm("mov.b64 %0, {%1, %2};" : "=l"(r) : "f"(lo), "f"(hi)); return r;
}
__device__ __forceinline__ void upk2(ull v, float& lo, float& hi) {
    asm("mov.b64 {%0, %1}, %2;" : "=f"(lo), "=f"(hi) : "l"(v));
}
__device__ __forceinline__ ull ffma2(ull a, ull b, ull c) {
    ull d; asm("fma.rn.f32x2 %0, %1, %2, %3;" : "=l"(d) : "l"(a), "l"(b), "l"(c)); return d;
}
__device__ __forceinline__ constexpr int skew(int c) { return c + (c >> 3); }

__global__ __launch_bounds__(THREADS) void fir6_kernel(
    const float* __restrict__ u, const float* __restrict__ kern,
    float* __restrict__ out, int cols, int out_cols, int K)
{
    __shared__ ull        s_p[NSLOT];   // skewed pair array
    __shared__ ulonglong2 s_w[PTAPS];   // (WE[t], WO[t]); one LDS.128 broadcast per tap

    const int tid  = threadIdx.x;
    const int row  = blockIdx.y;
    const int base = blockIdx.x * TILE;
    const float* urow = u + (size_t)row * cols;

    // w[k] = kern[K-1-k] reversed, zero-padded to 64.
    // WE[t] = (w[2t], w[2t+1]) : even outputs.  WO[t] = (w[2t-1], w[2t]) : odd outputs.
    if (tid < PTAPS) {
        const int t = tid;
        const float we0 = (2*t     < K) ? kern[K - 1 - 2*t]       : 0.0f;
        const float we1 = (2*t + 1 < K) ? kern[K - 1 - (2*t + 1)] : 0.0f;
        const float wo0 = (2*t >= 1 && 2*t - 1 < K) ? kern[K - 1 - (2*t - 1)] : 0.0f;
        s_w[t] = make_ulonglong2(pk2(we0, we1), pk2(wo0, we0));
    }

    // Stage input tile into skewed pair layout. Pair i = (u[base+2i], u[base+2i+1])
    // stored at slot i + i/8. Two pairs (2q, 2q+1) per float4 global load; they
    // share the same skew term so both STS.64 are adjacent slots.
    for (int q = tid; q < NPAIR / 2; q += THREADS) {
        const int gi = base + 4 * q;
        float4 v;
        if (gi + 3 < cols) {
            v = *reinterpret_cast<const float4*>(urow + gi);
        } else {
            v.x = (gi + 0 < cols) ? urow[gi + 0] : 0.0f;
            v.y = (gi + 1 < cols) ? urow[gi + 1] : 0.0f;
            v.z = (gi + 2 < cols) ? urow[gi + 2] : 0.0f;
            v.w = (gi + 3 < cols) ? urow[gi + 3] : 0.0f;
        }
        const int s = 2 * q + (q >> 2);     // slot(2q) = 2q + (2q>>3)
        s_p[s + 0] = pk2(v.x, v.y);
        s_p[s + 1] = pk2(v.z, v.w);
    }
    __syncthreads();

    const int bslot = 9 * tid;              // slot base: slot(8*tid + c) = 9*tid + skew(c)

    // Register window: win[r] = P[8*tid + t + r], r = 0..7.
    ull win[8];
    #pragma unroll
    for (int r = 0; r < 8; ++r) win[r] = s_p[bslot + skew(r)];

    ull Ae[8], Ao[8];
    #pragma unroll
    for (int r = 0; r < 8; ++r) { Ae[r] = 0ull; Ao[r] = 0ull; }

    #pragma unroll
    for (int t = 0; t < PTAPS; ++t) {
        const ulonglong2 W = s_w[t];        // LDS.128 broadcast
        #pragma unroll
        for (int r = 0; r < 8; ++r) {
            Ae[r] = ffma2(win[r], W.x, Ae[r]);
            Ao[r] = ffma2(win[r], W.y, Ao[r]);
        }
        #pragma unroll
        for (int r = 0; r < 7; ++r) win[r] = win[r + 1];   // renamed by unroll
        win[7] = s_p[bslot + skew(t + 8)];                 // refill P[8*tid + (t+1) + 7]
    }

    // Horizontal sums -> 16 consecutive outputs.
    float res[16];
    #pragma unroll
    for (int r = 0; r < 8; ++r) {
        float e0, e1, d0, d1;
        upk2(Ae[r], e0, e1); upk2(Ao[r], d0, d1);
        res[2*r + 0] = e0 + e1;
        res[2*r + 1] = d0 + d1;
    }

    const int oc = base + tid * OPT;        // 16-aligned
    float* orow = out + (size_t)row * out_cols;
    if (oc + OPT - 1 < out_cols) {
        #pragma unroll
        for (int q = 0; q < OPT / 4; ++q) {
            float4 v; v.x = res[4*q]; v.y = res[4*q+1]; v.z = res[4*q+2]; v.w = res[4*q+3];
            *reinterpret_cast<float4*>(orow + oc + 4*q) = v;
        }
    } else {
        #pragma unroll
        for (int k = 0; k < OPT; ++k)
            if (oc + k < out_cols) orow[oc + k] = res[k];
    }
}

extern "C" void kernel_launch(void* const* d_in, const int* in_sizes, int n_in,
                              void* d_out, int out_size)
{
    const float* u    = (const float*)d_in[0];
    const float* kern = (const float*)d_in[1];
    float*       out  = (float*)d_out;

    const int S0 = in_sizes[0];
    const int K  = in_sizes[1];
    const int rows     = (S0 - out_size) / (K - 1);
    const int cols     = S0 / rows;
    const int out_cols = cols - K + 1;

    dim3 grid((out_cols + TILE - 1) / TILE, rows);
    fir6_kernel<<<grid, THREADS>>>(u, kern, out, cols, out_cols, K);
}